// round 16
// baseline (speedup 1.0000x reference)
#include <cuda_runtime.h>
#include <cuda_bf16.h>
#include <cuda_fp16.h>
#include <cstdint>

#define N_NODES 10000
#define EDGES   160000
#define EMBED   128
#define HEADS   16
#define HC      2048
#define NEG_SLOPE 0.2f
#define M_SENT  (-1e30f)
#define MT      128
#define MPAD    (79 * 128)
#define ETILE   64

// ===================== device scratch =======================================
__device__ int   g_src[EDGES];
__device__ int   g_dst[EDGES];
__device__ int   g_deg[N_NODES];          // zero-init; re-zeroed by fill each call
__device__ int   g_rowptr[N_NODES + 1];
__device__ int   g_cursor[N_NODES];
__device__ int   g_col[EDGES + N_NODES];

__device__ float g_waS[HEADS * EMBED];
__device__ float g_waD[HEADS * EMBED];
__device__ __half g_w1t[(size_t)HC * EMBED];     // [n=2048][k=128] fp16
__device__ float g_vc[HC];                       // W2 @ Wc
__device__ float g_vs[HC];                       // W2 @ a_src2
__device__ float g_vd[HC];                       // W2 @ a_dst2
__device__ float g_const2;                       // b2.Wc + bc
__device__ float g_als1[MPAD * HEADS];
__device__ float g_ald1[MPAD * HEADS];
__device__ __half g_ax[(size_t)MPAD * HC];       // aggregated x per head, fp16
__device__ float g_c2[MPAD];                     // x2 . vc  (atomic accum)
__device__ float g_als2[MPAD];                   // x2 . vs
__device__ float g_ald2[MPAD];                   // x2 . vd

// ===================== L0: prep + decode + count ============================
template <int R, int C>
__device__ void transpose_cv(const float* __restrict__ src,
                             __half* __restrict__ dst, int bx, int by) {
    __shared__ float tile[32][33];
    int tx = threadIdx.x & 31, ty0 = threadIdx.x >> 5;
    #pragma unroll
    for (int j = 0; j < 4; j++) {
        int r = by * 32 + ty0 + j * 8, c = bx * 32 + tx;
        tile[ty0 + j * 8][tx] = src[(size_t)r * C + c];
    }
    __syncthreads();
    #pragma unroll
    for (int j = 0; j < 4; j++) {
        int rd = bx * 32 + ty0 + j * 8;
        int cd = by * 32 + tx;
        dst[(size_t)rd * R + cd] = __float2half(tile[tx][ty0 + j * 8]);
    }
}

#define NB_WA  16
#define NB_W1  256
#define NB_V   8
#define NB_PRE (NB_WA + NB_W1 + NB_V)

__global__ void prep_decode_kernel(const float* __restrict__ W1,
                                   const float* __restrict__ W2,
                                   const float* __restrict__ as1,
                                   const float* __restrict__ ad1,
                                   const float* __restrict__ as2,
                                   const float* __restrict__ ad2,
                                   const float* __restrict__ b2,
                                   const float* __restrict__ Wc,
                                   const float* __restrict__ bc,
                                   const void* __restrict__ ei, int E) {
    int b = blockIdx.x, t = threadIdx.x;
    if (b < NB_WA) {
        __shared__ float sa[EMBED], sd[EMBED];
        int h = b;
        if (t < 128) { sa[t] = as1[h * EMBED + t]; sd[t] = ad1[h * EMBED + t]; }
        __syncthreads();
        if (t < 128) {
            float ss = 0.f, ssd = 0.f;
            const float* wrow = W1 + (size_t)t * HC + h * EMBED;
            #pragma unroll 4
            for (int c = 0; c < EMBED; c++) {
                float w = wrow[c];
                ss += w * sa[c];
                ssd += w * sd[c];
            }
            g_waS[h * EMBED + t] = ss;
            g_waD[h * EMBED + t] = ssd;
        }
        return;
    }
    b -= NB_WA;
    if (b < NB_W1) { transpose_cv<128, 2048>(W1, g_w1t, b & 63, b >> 6); return; }
    b -= NB_W1;
    if (b < NB_V) {   // v vectors: one row of W2 per thread
        int k = b * 256 + t;     // 0..2047
        const float* wrow = W2 + (size_t)k * EMBED;
        float sc = 0.f, ss = 0.f, sd = 0.f;
        #pragma unroll 4
        for (int c = 0; c < EMBED; c++) {
            float w = wrow[c];
            sc += w * __ldg(&Wc[c]);
            ss += w * __ldg(&as2[c]);
            sd += w * __ldg(&ad2[c]);
        }
        g_vc[k] = sc;
        g_vs[k] = ss;
        g_vd[k] = sd;
        if (b == 0 && t < 32) {  // const2 = b2.Wc + bc
            float s = 0.f;
            for (int c = t; c < EMBED; c += 32) s += b2[c] * Wc[c];
            #pragma unroll
            for (int o = 16; o > 0; o >>= 1) s += __shfl_down_sync(0xffffffffu, s, o);
            if (t == 0) g_const2 = s + bc[0];
        }
        return;
    }
    b -= NB_V;
    const long long* p64 = (const long long*)ei;
    long long pv = p64[t];
    int ok = (pv >= 0 && pv < N_NODES);
    int is64 = __syncthreads_and(ok);
    int i = b * 256 + t;
    if (i >= 2 * E) return;
    int vi = is64 ? (int)p64[i] : ((const int*)ei)[i];
    if (i < E) g_src[i] = vi;
    else { g_dst[i - E] = vi; atomicAdd(&g_deg[vi], 1); }
}

// ===================== L1: scan (block 0) + logits1 =========================
__global__ void scan_logits_kernel(const float* __restrict__ x, int n) {
    int t = threadIdx.x;
    if (blockIdx.x == 0) {
        __shared__ int wsum[32];
        int CH = (n + 1023) / 1024;
        int base = t * CH;
        int s = 0;
        for (int k = 0; k < CH; k++) { int idx = base + k; if (idx < n) s += g_deg[idx] + 1; }
        int lane = t & 31, wid = t >> 5;
        int v = s;
        #pragma unroll
        for (int o = 1; o < 32; o <<= 1) {
            int t2 = __shfl_up_sync(0xffffffffu, v, o);
            if (lane >= o) v += t2;
        }
        if (lane == 31) wsum[wid] = v;
        __syncthreads();
        if (wid == 0) {
            int w = wsum[lane];
            #pragma unroll
            for (int o = 1; o < 32; o <<= 1) {
                int t2 = __shfl_up_sync(0xffffffffu, w, o);
                if (lane >= o) w += t2;
            }
            wsum[lane] = w;
        }
        __syncthreads();
        int excl = v - s + (wid ? wsum[wid - 1] : 0);
        int running = excl;
        for (int k = 0; k < CH; k++) {
            int idx = base + k;
            if (idx < n) {
                g_rowptr[idx] = running;
                g_cursor[idx] = running;
                running += g_deg[idx] + 1;
            }
        }
        if (t == 0) g_rowptr[n] = wsum[31];
        return;
    }
    int node = (blockIdx.x - 1) * 32 + (t >> 5);
    if (node >= n) return;
    int lane = t & 31;
    float4 xv = ((const float4*)(x + (size_t)node * EMBED))[lane];
    #pragma unroll
    for (int h = 0; h < HEADS; h++) {
        float4 wS = ((const float4*)(g_waS + h * EMBED))[lane];
        float4 wD = ((const float4*)(g_waD + h * EMBED))[lane];
        float ss = xv.x * wS.x + xv.y * wS.y + xv.z * wS.z + xv.w * wS.w;
        float sd = xv.x * wD.x + xv.y * wD.y + xv.z * wD.z + xv.w * wD.w;
        #pragma unroll
        for (int o = 16; o > 0; o >>= 1) {
            ss += __shfl_xor_sync(0xffffffffu, ss, o);
            sd += __shfl_xor_sync(0xffffffffu, sd, o);
        }
        if (lane == 0) {
            g_als1[node * HEADS + h] = ss;
            g_ald1[node * HEADS + h] = sd;
        }
    }
}

// ===================== L2: fill (+ zero accum arrays + deg self-clean) ======
__global__ void fill_kernel(int E, int n) {
    int i = blockIdx.x * blockDim.x + threadIdx.x;
    if (i < E) {
        int d = g_dst[i];
        int pos = atomicAdd(&g_cursor[d], 1);
        g_col[pos] = g_src[i];
    } else {
        int v = i - E;
        if (v < MPAD) { g_c2[v] = 0.f; g_als2[v] = 0.f; g_ald2[v] = 0.f; }
        if (v < n) {
            int pos = atomicAdd(&g_cursor[v], 1);
            g_col[pos] = v;
            g_deg[v] = 0;
        }
    }
}

// ===================== L3 (PROFILED): agg1, 8 heads per block ===============
// grid (n, 2): blockIdx.y selects head half [hb*8, hb*8+8)
__global__ __launch_bounds__(128) void agg1_kernel(const float* __restrict__ x) {
    int nno = blockIdx.x;
    int hb = blockIdx.y;               // 0 or 1
    int t = threadIdx.x;               // 128; phase2: t = channel
    int beg = g_rowptr[nno];
    int deg = g_rowptr[nno + 1] - beg;
    int h = t & 7, sub = t >> 3;       // phase1: 8 heads x 16 subs
    int warp = t >> 5, lane = t & 31;

    __shared__ float s_ad[8], s_run_m[8], s_run_s[8], s_scale[8], s_inv[8];
    __shared__ float s_pm[4][8], s_ps[4][8];
    __shared__ int   s_src[ETILE];
    __shared__ float sw[ETILE][8];

    if (t < 8) {
        s_ad[t] = g_ald1[nno * HEADS + hb * 8 + t];
        s_run_m[t] = M_SENT;
        s_run_s[t] = 0.f;
    }
    float acc[8];
    #pragma unroll
    for (int i = 0; i < 8; i++) acc[i] = 0.f;
    __syncthreads();

    int hg = hb * 8 + h;               // global head for phase-1 loads

    for (int e0 = 0; e0 < deg; e0 += ETILE) {
        int ne = min(ETILE, deg - e0);
        if (t < ne) s_src[t] = __ldg(&g_col[beg + e0 + t]);
        __syncthreads();
        // single gather: raw leaky logits into sw
        for (int k = t; k < ne * 8; k += 128) {
            int e = k >> 3;                        // h == t&7 invariant
            float lg = __ldg(&g_als1[s_src[e] * HEADS + hg]) + s_ad[h];
            sw[e][h] = lg > 0.f ? lg : NEG_SLOPE * lg;
        }
        __syncthreads();
        // tile max per head (16-way)
        float tm = M_SENT;
        for (int e = sub; e < ne; e += 16) tm = fmaxf(tm, sw[e][h]);
        tm = fmaxf(tm, __shfl_xor_sync(0xffffffffu, tm, 8));
        tm = fmaxf(tm, __shfl_xor_sync(0xffffffffu, tm, 16));
        if (lane < 8) s_pm[warp][h] = tm;
        __syncthreads();
        if (t < 8) {
            float mt = fmaxf(fmaxf(s_pm[0][t], s_pm[1][t]), fmaxf(s_pm[2][t], s_pm[3][t]));
            float nm = fmaxf(s_run_m[t], mt);
            float sc = __expf(s_run_m[t] - nm);
            s_scale[t] = sc;
            s_run_m[t] = nm;
            s_run_s[t] *= sc;
        }
        __syncthreads();
        // one exp per entry; partial sums per head
        float psum = 0.f;
        for (int k = t; k < ne * 8; k += 128) {
            int e = k >> 3;
            float w = __expf(sw[e][h] - s_run_m[h]);
            sw[e][h] = w;
            psum += w;
        }
        psum += __shfl_xor_sync(0xffffffffu, psum, 8);
        psum += __shfl_xor_sync(0xffffffffu, psum, 16);
        if (lane < 8) s_ps[warp][h] = psum;
        __syncthreads();
        if (t < 8)
            s_run_s[t] += s_ps[0][t] + s_ps[1][t] + s_ps[2][t] + s_ps[3][t];
        #pragma unroll
        for (int i = 0; i < 8; i++) acc[i] *= s_scale[i];
        // weighted accumulation
        #pragma unroll 2
        for (int e = 0; e < ne; e++) {
            float xv = __ldg(&x[(size_t)s_src[e] * EMBED + t]);
            float4 w0 = *(float4*)&sw[e][0];
            float4 w1 = *(float4*)&sw[e][4];
            acc[0] += w0.x * xv;  acc[1] += w0.y * xv;
            acc[2] += w0.z * xv;  acc[3] += w0.w * xv;
            acc[4] += w1.x * xv;  acc[5] += w1.y * xv;
            acc[6] += w1.z * xv;  acc[7] += w1.w * xv;
        }
        __syncthreads();
    }
    if (t < 8) s_inv[t] = 1.f / (s_run_s[t] + 1e-16f);
    __syncthreads();
    #pragma unroll
    for (int i = 0; i < 8; i++)
        g_ax[(size_t)nno * HC + (hb * 8 + i) * EMBED + t] = __float2half(acc[i] * s_inv[i]);
}

// ===================== mma.sync fp16 GEMM machinery =========================
#define SKW 72
#define CHUNK_B (128 * SKW * 2)

__device__ __forceinline__ void mma16816(float* c, const uint32_t* a, const uint32_t* b) {
    asm volatile("mma.sync.aligned.m16n8k16.row.col.f32.f16.f16.f32 "
        "{%0,%1,%2,%3}, {%4,%5,%6,%7}, {%8,%9}, {%0,%1,%2,%3};"
        : "+f"(c[0]), "+f"(c[1]), "+f"(c[2]), "+f"(c[3])
        : "r"(a[0]), "r"(a[1]), "r"(a[2]), "r"(a[3]), "r"(b[0]), "r"(b[1]));
}

__device__ __forceinline__ void fetch_chunk(const __half* __restrict__ src,
                                            int ld, int row0, int k0,
                                            float4* r, int tid) {
    #pragma unroll
    for (int i = 0; i < 4; i++) {
        int c = tid + i * 256;
        int row = c >> 3;
        int kk = (c & 7) * 8;
        r[i] = *(const float4*)(src + (size_t)(row0 + row) * ld + k0 + kk);
    }
}

__device__ __forceinline__ void stash_chunk(const float4* r,
                                            __half (*S)[SKW], int tid) {
    #pragma unroll
    for (int i = 0; i < 4; i++) {
        int c = tid + i * 256;
        int row = c >> 3;
        int kk = (c & 7) * 8;
        *(float4*)&S[row][kk] = r[i];
    }
}

__device__ __forceinline__ void mma_chunk(const __half (*As)[SKW],
                                          const __half (*Bs)[SKW],
                                          float c[2][8][4],
                                          int warp_m, int warp_n, int lane) {
    int g = lane >> 2, tig = lane & 3;
    #pragma unroll
    for (int ks = 0; ks < 4; ks++) {
        int k0 = ks * 16;
        uint32_t a[2][4], b[8][2];
        #pragma unroll
        for (int mt = 0; mt < 2; mt++) {
            int r = warp_m * 32 + mt * 16 + g;
            a[mt][0] = *(const uint32_t*)&As[r][k0 + tig * 2];
            a[mt][1] = *(const uint32_t*)&As[r + 8][k0 + tig * 2];
            a[mt][2] = *(const uint32_t*)&As[r][k0 + tig * 2 + 8];
            a[mt][3] = *(const uint32_t*)&As[r + 8][k0 + tig * 2 + 8];
        }
        #pragma unroll
        for (int nt = 0; nt < 8; nt++) {
            int n = warp_n * 64 + nt * 8 + g;
            b[nt][0] = *(const uint32_t*)&Bs[n][k0 + tig * 2];
            b[nt][1] = *(const uint32_t*)&Bs[n][k0 + tig * 2 + 8];
        }
        #pragma unroll
        for (int mt = 0; mt < 2; mt++)
            #pragma unroll
            for (int nt = 0; nt < 8; nt++)
                mma16816(c[mt][nt], a[mt], b[nt]);
    }
}

// ===================== L4: expand1 = ELU(aggx @ W1_h + b1) + fused dots =====
#define G1_SMEM (4 * CHUNK_B + 4 * 128 * 4)

__global__ __launch_bounds__(256) void expand1_kernel(const float* __restrict__ b1) {
    extern __shared__ char dsm[];
    __half (*Ab[2])[SKW] = {(__half(*)[SKW])dsm, (__half(*)[SKW])(dsm + 2 * CHUNK_B)};
    __half (*Bb[2])[SKW] = {(__half(*)[SKW])(dsm + CHUNK_B),
                            (__half(*)[SKW])(dsm + 3 * CHUNK_B)};
    float* s_b  = (float*)(dsm + 4 * CHUNK_B);
    float* s_vc = s_b + 128;
    float* s_vs = s_vc + 128;
    float* s_vd = s_vs + 128;

    int tid = threadIdx.x;
    int wid = tid >> 5, lane = tid & 31;
    int warp_m = wid & 3, warp_n = wid >> 2;
    int g = lane >> 2, tig = lane & 3;
    int h = blockIdx.x;
    int m0 = blockIdx.y * MT;

    if (tid < 128) {
        s_b[tid]  = b1[h * EMBED + tid];
        s_vc[tid] = g_vc[h * EMBED + tid];
        s_vs[tid] = g_vs[h * EMBED + tid];
        s_vd[tid] = g_vd[h * EMBED + tid];
    }

    float c[2][8][4];
    #pragma unroll
    for (int mt = 0; mt < 2; mt++)
        #pragma unroll
        for (int nt = 0; nt < 8; nt++)
            #pragma unroll
            for (int i = 0; i < 4; i++) c[mt][nt][i] = 0.f;

    float4 pa[4], pb[4];
    fetch_chunk(g_ax, HC, m0, h * EMBED, pa, tid);
    fetch_chunk(g_w1t, EMBED, h * 128, 0, pb, tid);
    #pragma unroll
    for (int it = 0; it < 2; it++) {
        stash_chunk(pa, Ab[it & 1], tid);
        stash_chunk(pb, Bb[it & 1], tid);
        __syncthreads();
        if (it == 0) {
            fetch_chunk(g_ax, HC, m0, h * EMBED + 64, pa, tid);
            fetch_chunk(g_w1t, EMBED, h * 128, 64, pb, tid);
        }
        mma_chunk(Ab[it & 1], Bb[it & 1], c, warp_m, warp_n, lane);
        __syncthreads();
    }

    // epilogue: bias + ELU + dot partials against v-slices (no x2 store)
    float pc[4] = {0.f, 0.f, 0.f, 0.f};
    float ps[4] = {0.f, 0.f, 0.f, 0.f};
    float pd[4] = {0.f, 0.f, 0.f, 0.f};
    #pragma unroll
    for (int mt = 0; mt < 2; mt++) {
        #pragma unroll
        for (int nt = 0; nt < 8; nt++) {
            int col = warp_n * 64 + nt * 8 + tig * 2;
            float* cc = c[mt][nt];
            #pragma unroll
            for (int q = 0; q < 2; q++) {
                float v0 = cc[q * 2 + 0] + s_b[col];
                float v1 = cc[q * 2 + 1] + s_b[col + 1];
                v0 = v0 > 0.f ? v0 : (__expf(v0) - 1.f);
                v1 = v1 > 0.f ? v1 : (__expf(v1) - 1.f);
                int slot = mt * 2 + q;
                pc[slot] += v0 * s_vc[col] + v1 * s_vc[col + 1];
                ps[slot] += v0 * s_vs[col] + v1 * s_vs[col + 1];
                pd[slot] += v0 * s_vd[col] + v1 * s_vd[col + 1];
            }
        }
    }
    #pragma unroll
    for (int o = 1; o <= 2; o <<= 1) {
        #pragma unroll
        for (int s = 0; s < 4; s++) {
            pc[s] += __shfl_xor_sync(0xffffffffu, pc[s], o);
            ps[s] += __shfl_xor_sync(0xffffffffu, ps[s], o);
            pd[s] += __shfl_xor_sync(0xffffffffu, pd[s], o);
        }
    }
    if (tig == 0) {
        #pragma unroll
        for (int mt = 0; mt < 2; mt++)
            #pragma unroll
            for (int q = 0; q < 2; q++) {
                int row = m0 + warp_m * 32 + mt * 16 + q * 8 + g;
                int slot = mt * 2 + q;
                atomicAdd(&g_c2[row], pc[slot]);
                atomicAdd(&g_als2[row], ps[slot]);
                atomicAdd(&g_ald2[row], pd[slot]);
            }
    }
}

// ===================== L5: agg2 scalar softmax + classifier =================
__global__ void agg2_kernel(float* __restrict__ out, int n) {
    int node = blockIdx.x * 8 + (threadIdx.x >> 5);
    if (node >= n) return;
    int lane = threadIdx.x & 31;
    int beg = g_rowptr[node];
    int deg = g_rowptr[node + 1] - beg;
    float ad = g_ald2[node];

    float m = M_SENT, s = 0.f, acc = 0.f;
    for (int j = lane; j < deg; j += 32) {
        int src = __ldg(&g_col[beg + j]);
        float lg = __ldg(&g_als2[src]) + ad;
        lg = lg > 0.f ? lg : NEG_SLOPE * lg;
        float c2 = __ldg(&g_c2[src]);
        if (lg > m) {
            float sc = __expf(m - lg);
            s = s * sc + 1.f;
            acc = acc * sc + c2;
            m = lg;
        } else {
            float p = __expf(lg - m);
            s += p;
            acc += p * c2;
        }
    }
    #pragma unroll
    for (int o = 16; o > 0; o >>= 1) {
        float om = __shfl_xor_sync(0xffffffffu, m, o);
        float os = __shfl_xor_sync(0xffffffffu, s, o);
        float oa = __shfl_xor_sync(0xffffffffu, acc, o);
        float nm = fmaxf(m, om);
        float e1 = __expf(m - nm), e2 = __expf(om - nm);
        s = s * e1 + os * e2;
        acc = acc * e1 + oa * e2;
        m = nm;
    }
    if (lane == 0) out[node] = acc / (s + 1e-16f) + g_const2;
}

// ===================== launch ===============================================
extern "C" void kernel_launch(void* const* d_in, const int* in_sizes, int n_in,
                              void* d_out, int out_size) {
    const float* x   = (const float*)d_in[0];
    const void*  ei  = d_in[1];
    const float* W1  = (const float*)d_in[2];
    const float* as1 = (const float*)d_in[3];
    const float* ad1 = (const float*)d_in[4];
    const float* b1  = (const float*)d_in[5];
    const float* W2  = (const float*)d_in[6];
    const float* as2 = (const float*)d_in[7];
    const float* ad2 = (const float*)d_in[8];
    const float* b2  = (const float*)d_in[9];
    const float* Wc  = (const float*)d_in[10];
    const float* bc  = (const float*)d_in[11];
    float* out = (float*)d_out;

    int E = in_sizes[1] / 2;
    int n = in_sizes[0] / EMBED;
    int mtiles = (n + MT - 1) / MT;

    cudaFuncSetAttribute(expand1_kernel, cudaFuncAttributeMaxDynamicSharedMemorySize, G1_SMEM);

    int decode_blocks = (2 * E + 255) / 256;
    prep_decode_kernel<<<NB_PRE + decode_blocks, 256>>>(W1, W2, as1, ad1, as2, ad2,
                                                        b2, Wc, bc, ei, E);       // 0
    scan_logits_kernel<<<1 + (n + 31) / 32, 1024>>>(x, n);                        // 1
    fill_kernel<<<(E + MPAD + 255) / 256, 256>>>(E, n);                           // 2
    agg1_kernel<<<dim3(n, 2), 128>>>(x);                                          // 3 <- profiled
    expand1_kernel<<<dim3(HEADS, mtiles), 256, G1_SMEM>>>(b1);                    // 4
    agg2_kernel<<<(n + 7) / 8, 256>>>(out, n);                                    // 5
}

// round 17
// speedup vs baseline: 1.1453x; 1.1453x over previous
#include <cuda_runtime.h>
#include <cuda_bf16.h>
#include <cuda_fp16.h>
#include <cstdint>

#define N_NODES 10000
#define EDGES   160000
#define EMBED   128
#define HEADS   16
#define HC      2048
#define NEG_SLOPE 0.2f
#define M_SENT  (-1e30f)
#define MT      128
#define MPAD    (79 * 128)
#define ETILE   64

// ===================== device scratch =======================================
__device__ int   g_src[EDGES];
__device__ int   g_dst[EDGES];
__device__ int   g_deg[N_NODES];          // zero-init; re-zeroed by fill each call
__device__ int   g_rowptr[N_NODES + 1];
__device__ int   g_cursor[N_NODES];
__device__ int   g_col[EDGES + N_NODES];

__device__ float g_waS[HEADS * EMBED];
__device__ float g_waD[HEADS * EMBED];
__device__ __half g_w1t[(size_t)HC * EMBED];     // [n=2048][k=128] fp16
__device__ float g_vc[HC];                       // W2 @ Wc
__device__ float g_vs[HC];                       // W2 @ a_src2
__device__ float g_vd[HC];                       // W2 @ a_dst2
__device__ float g_const2;                       // b2.Wc + bc
__device__ float g_als1[MPAD * HEADS];
__device__ float g_ald1[MPAD * HEADS];
__device__ __half g_ax[(size_t)MPAD * HC];       // aggregated x per head, fp16
__device__ float g_c2[MPAD];                     // x2 . vc  (atomic accum)
__device__ float g_als2[MPAD];                   // x2 . vs
__device__ float g_ald2[MPAD];                   // x2 . vd

// ===================== L0: prep + decode + count ============================
template <int R, int C>
__device__ void transpose_cv(const float* __restrict__ src,
                             __half* __restrict__ dst, int bx, int by) {
    __shared__ float tile[32][33];
    int tx = threadIdx.x & 31, ty0 = threadIdx.x >> 5;
    #pragma unroll
    for (int j = 0; j < 4; j++) {
        int r = by * 32 + ty0 + j * 8, c = bx * 32 + tx;
        tile[ty0 + j * 8][tx] = src[(size_t)r * C + c];
    }
    __syncthreads();
    #pragma unroll
    for (int j = 0; j < 4; j++) {
        int rd = bx * 32 + ty0 + j * 8;
        int cd = by * 32 + tx;
        dst[(size_t)rd * R + cd] = __float2half(tile[tx][ty0 + j * 8]);
    }
}

#define NB_WA  16
#define NB_W1  256
#define NB_V   8
#define NB_PRE (NB_WA + NB_W1 + NB_V)

__global__ void prep_decode_kernel(const float* __restrict__ W1,
                                   const float* __restrict__ W2,
                                   const float* __restrict__ as1,
                                   const float* __restrict__ ad1,
                                   const float* __restrict__ as2,
                                   const float* __restrict__ ad2,
                                   const float* __restrict__ b2,
                                   const float* __restrict__ Wc,
                                   const float* __restrict__ bc,
                                   const void* __restrict__ ei, int E) {
    int b = blockIdx.x, t = threadIdx.x;
    if (b < NB_WA) {
        __shared__ float sa[EMBED], sd[EMBED];
        int h = b;
        if (t < 128) { sa[t] = as1[h * EMBED + t]; sd[t] = ad1[h * EMBED + t]; }
        __syncthreads();
        if (t < 128) {
            float ss = 0.f, ssd = 0.f;
            const float* wrow = W1 + (size_t)t * HC + h * EMBED;
            #pragma unroll 4
            for (int c = 0; c < EMBED; c++) {
                float w = wrow[c];
                ss += w * sa[c];
                ssd += w * sd[c];
            }
            g_waS[h * EMBED + t] = ss;
            g_waD[h * EMBED + t] = ssd;
        }
        return;
    }
    b -= NB_WA;
    if (b < NB_W1) { transpose_cv<128, 2048>(W1, g_w1t, b & 63, b >> 6); return; }
    b -= NB_W1;
    if (b < NB_V) {   // v vectors: one row of W2 per thread
        int k = b * 256 + t;     // 0..2047
        const float* wrow = W2 + (size_t)k * EMBED;
        float sc = 0.f, ss = 0.f, sd = 0.f;
        #pragma unroll 4
        for (int c = 0; c < EMBED; c++) {
            float w = wrow[c];
            sc += w * __ldg(&Wc[c]);
            ss += w * __ldg(&as2[c]);
            sd += w * __ldg(&ad2[c]);
        }
        g_vc[k] = sc;
        g_vs[k] = ss;
        g_vd[k] = sd;
        if (b == 0 && t < 32) {  // const2 = b2.Wc + bc
            float s = 0.f;
            for (int c = t; c < EMBED; c += 32) s += b2[c] * Wc[c];
            #pragma unroll
            for (int o = 16; o > 0; o >>= 1) s += __shfl_down_sync(0xffffffffu, s, o);
            if (t == 0) g_const2 = s + bc[0];
        }
        return;
    }
    b -= NB_V;
    const long long* p64 = (const long long*)ei;
    long long pv = p64[t];
    int ok = (pv >= 0 && pv < N_NODES);
    int is64 = __syncthreads_and(ok);
    int i = b * 256 + t;
    if (i >= 2 * E) return;
    int vi = is64 ? (int)p64[i] : ((const int*)ei)[i];
    if (i < E) g_src[i] = vi;
    else { g_dst[i - E] = vi; atomicAdd(&g_deg[vi], 1); }
}

// ===================== L1: scan (block 0) + logits1 =========================
__global__ void scan_logits_kernel(const float* __restrict__ x, int n) {
    int t = threadIdx.x;
    if (blockIdx.x == 0) {
        __shared__ int wsum[32];
        int CH = (n + 1023) / 1024;
        int base = t * CH;
        int s = 0;
        for (int k = 0; k < CH; k++) { int idx = base + k; if (idx < n) s += g_deg[idx] + 1; }
        int lane = t & 31, wid = t >> 5;
        int v = s;
        #pragma unroll
        for (int o = 1; o < 32; o <<= 1) {
            int t2 = __shfl_up_sync(0xffffffffu, v, o);
            if (lane >= o) v += t2;
        }
        if (lane == 31) wsum[wid] = v;
        __syncthreads();
        if (wid == 0) {
            int w = wsum[lane];
            #pragma unroll
            for (int o = 1; o < 32; o <<= 1) {
                int t2 = __shfl_up_sync(0xffffffffu, w, o);
                if (lane >= o) w += t2;
            }
            wsum[lane] = w;
        }
        __syncthreads();
        int excl = v - s + (wid ? wsum[wid - 1] : 0);
        int running = excl;
        for (int k = 0; k < CH; k++) {
            int idx = base + k;
            if (idx < n) {
                g_rowptr[idx] = running;
                g_cursor[idx] = running;
                running += g_deg[idx] + 1;
            }
        }
        if (t == 0) g_rowptr[n] = wsum[31];
        return;
    }
    int node = (blockIdx.x - 1) * 32 + (t >> 5);
    if (node >= n) return;
    int lane = t & 31;
    float4 xv = ((const float4*)(x + (size_t)node * EMBED))[lane];
    #pragma unroll
    for (int h = 0; h < HEADS; h++) {
        float4 wS = ((const float4*)(g_waS + h * EMBED))[lane];
        float4 wD = ((const float4*)(g_waD + h * EMBED))[lane];
        float ss = xv.x * wS.x + xv.y * wS.y + xv.z * wS.z + xv.w * wS.w;
        float sd = xv.x * wD.x + xv.y * wD.y + xv.z * wD.z + xv.w * wD.w;
        #pragma unroll
        for (int o = 16; o > 0; o >>= 1) {
            ss += __shfl_xor_sync(0xffffffffu, ss, o);
            sd += __shfl_xor_sync(0xffffffffu, sd, o);
        }
        if (lane == 0) {
            g_als1[node * HEADS + h] = ss;
            g_ald1[node * HEADS + h] = sd;
        }
    }
}

// ===================== L2: fill (+ zero accum arrays + deg self-clean) ======
__global__ void fill_kernel(int E, int n) {
    int i = blockIdx.x * blockDim.x + threadIdx.x;
    if (i < E) {
        int d = g_dst[i];
        int pos = atomicAdd(&g_cursor[d], 1);
        g_col[pos] = g_src[i];
    } else {
        int v = i - E;
        if (v < MPAD) { g_c2[v] = 0.f; g_als2[v] = 0.f; g_ald2[v] = 0.f; }
        if (v < n) {
            int pos = atomicAdd(&g_cursor[v], 1);
            g_col[pos] = v;
            g_deg[v] = 0;
        }
    }
}

// ===================== L3 (PROFILED): agg1, f32x2 packed FMA ================
__global__ __launch_bounds__(128) void agg1_kernel(const float* __restrict__ x) {
    int nno = blockIdx.x;
    int t = threadIdx.x;               // 128; phase2: t = channel
    int beg = g_rowptr[nno];
    int deg = g_rowptr[nno + 1] - beg;
    int h = t & 15, sub = t >> 4;
    int warp = t >> 5, lane = t & 31;

    __shared__ float s_ad[16], s_run_m[16], s_run_s[16], s_scale[16], s_inv[16];
    __shared__ float s_pm[4][16], s_ps[4][16];
    __shared__ int   s_src[ETILE];
    __shared__ float sw[ETILE][16];    // rows are 64B: v2.u64-aligned

    if (t < 16) {
        s_ad[t] = g_ald1[nno * HEADS + t];
        s_run_m[t] = M_SENT;
        s_run_s[t] = 0.f;
    }
    uint64_t acc2[8];                  // 16 fp32 accumulators as f32x2 pairs
    #pragma unroll
    for (int i = 0; i < 8; i++) acc2[i] = 0ull;

    uint32_t sw_base;
    asm("{ .reg .u64 tt; cvta.to.shared.u64 tt, %1; cvt.u32.u64 %0, tt; }"
        : "=r"(sw_base) : "l"(&sw[0][0]));
    __syncthreads();

    for (int e0 = 0; e0 < deg; e0 += ETILE) {
        int ne = min(ETILE, deg - e0);
        if (t < ne) s_src[t] = __ldg(&g_col[beg + e0 + t]);
        __syncthreads();
        // single gather: raw leaky logits into sw
        for (int k = t; k < ne * 16; k += 128) {
            int e = k >> 4;                         // h == t&15 invariant
            float lg = __ldg(&g_als1[s_src[e] * HEADS + h]) + s_ad[h];
            sw[e][h] = lg > 0.f ? lg : NEG_SLOPE * lg;
        }
        __syncthreads();
        // tile max per head
        float tm = M_SENT;
        for (int e = sub; e < ne; e += 8) tm = fmaxf(tm, sw[e][h]);
        tm = fmaxf(tm, __shfl_xor_sync(0xffffffffu, tm, 16));
        if (lane < 16) s_pm[warp][h] = tm;
        __syncthreads();
        if (t < 16) {
            float mt = fmaxf(fmaxf(s_pm[0][t], s_pm[1][t]), fmaxf(s_pm[2][t], s_pm[3][t]));
            float nm = fmaxf(s_run_m[t], mt);
            float sc = __expf(s_run_m[t] - nm);
            s_scale[t] = sc;
            s_run_m[t] = nm;
            s_run_s[t] *= sc;
        }
        __syncthreads();
        // one exp per entry
        float psum = 0.f;
        for (int k = t; k < ne * 16; k += 128) {
            int e = k >> 4;
            float w = __expf(sw[e][h] - s_run_m[h]);
            sw[e][h] = w;
            psum += w;
        }
        psum += __shfl_xor_sync(0xffffffffu, psum, 16);
        if (lane < 16) s_ps[warp][h] = psum;
        __syncthreads();
        if (t < 16)
            s_run_s[t] += s_ps[0][t] + s_ps[1][t] + s_ps[2][t] + s_ps[3][t];
        // rescale accumulators (packed)
        #pragma unroll
        for (int i = 0; i < 8; i++) {
            uint64_t sc2 = *(const uint64_t*)&s_scale[2 * i];
            asm("mul.rn.f32x2 %0, %0, %1;" : "+l"(acc2[i]) : "l"(sc2));
        }
        // weighted accumulation: packed f32x2 FMAs
        for (int e = 0; e < ne; e++) {
            float xv = __ldg(&x[(size_t)s_src[e] * EMBED + t]);
            uint64_t xv2;
            asm("mov.b64 %0, {%1, %1};" : "=l"(xv2) : "f"(xv));
            uint32_t a0 = sw_base + e * 64;
            uint64_t w0, w1, w2, w3, w4, w5, w6, w7;
            asm("ld.shared.v2.u64 {%0,%1}, [%2];" : "=l"(w0), "=l"(w1) : "r"(a0));
            asm("ld.shared.v2.u64 {%0,%1}, [%2];" : "=l"(w2), "=l"(w3) : "r"(a0 + 16));
            asm("ld.shared.v2.u64 {%0,%1}, [%2];" : "=l"(w4), "=l"(w5) : "r"(a0 + 32));
            asm("ld.shared.v2.u64 {%0,%1}, [%2];" : "=l"(w6), "=l"(w7) : "r"(a0 + 48));
            asm("fma.rn.f32x2 %0, %1, %2, %0;" : "+l"(acc2[0]) : "l"(w0), "l"(xv2));
            asm("fma.rn.f32x2 %0, %1, %2, %0;" : "+l"(acc2[1]) : "l"(w1), "l"(xv2));
            asm("fma.rn.f32x2 %0, %1, %2, %0;" : "+l"(acc2[2]) : "l"(w2), "l"(xv2));
            asm("fma.rn.f32x2 %0, %1, %2, %0;" : "+l"(acc2[3]) : "l"(w3), "l"(xv2));
            asm("fma.rn.f32x2 %0, %1, %2, %0;" : "+l"(acc2[4]) : "l"(w4), "l"(xv2));
            asm("fma.rn.f32x2 %0, %1, %2, %0;" : "+l"(acc2[5]) : "l"(w5), "l"(xv2));
            asm("fma.rn.f32x2 %0, %1, %2, %0;" : "+l"(acc2[6]) : "l"(w6), "l"(xv2));
            asm("fma.rn.f32x2 %0, %1, %2, %0;" : "+l"(acc2[7]) : "l"(w7), "l"(xv2));
        }
        __syncthreads();
    }
    if (t < 16) s_inv[t] = 1.f / (s_run_s[t] + 1e-16f);
    __syncthreads();
    size_t base = (size_t)nno * HC;
    #pragma unroll
    for (int i = 0; i < 8; i++) {
        float lo, hi;
        asm("mov.b64 {%0,%1}, %2;" : "=f"(lo), "=f"(hi) : "l"(acc2[i]));
        g_ax[base + (2 * i) * EMBED + t]     = __float2half(lo * s_inv[2 * i]);
        g_ax[base + (2 * i + 1) * EMBED + t] = __float2half(hi * s_inv[2 * i + 1]);
    }
}

// ===================== mma.sync fp16 GEMM machinery =========================
#define SKW 72
#define CHUNK_B (128 * SKW * 2)

__device__ __forceinline__ void mma16816(float* c, const uint32_t* a, const uint32_t* b) {
    asm volatile("mma.sync.aligned.m16n8k16.row.col.f32.f16.f16.f32 "
        "{%0,%1,%2,%3}, {%4,%5,%6,%7}, {%8,%9}, {%0,%1,%2,%3};"
        : "+f"(c[0]), "+f"(c[1]), "+f"(c[2]), "+f"(c[3])
        : "r"(a[0]), "r"(a[1]), "r"(a[2]), "r"(a[3]), "r"(b[0]), "r"(b[1]));
}

__device__ __forceinline__ void fetch_chunk(const __half* __restrict__ src,
                                            int ld, int row0, int k0,
                                            float4* r, int tid) {
    #pragma unroll
    for (int i = 0; i < 4; i++) {
        int c = tid + i * 256;
        int row = c >> 3;
        int kk = (c & 7) * 8;
        r[i] = *(const float4*)(src + (size_t)(row0 + row) * ld + k0 + kk);
    }
}

__device__ __forceinline__ void stash_chunk(const float4* r,
                                            __half (*S)[SKW], int tid) {
    #pragma unroll
    for (int i = 0; i < 4; i++) {
        int c = tid + i * 256;
        int row = c >> 3;
        int kk = (c & 7) * 8;
        *(float4*)&S[row][kk] = r[i];
    }
}

__device__ __forceinline__ void mma_chunk(const __half (*As)[SKW],
                                          const __half (*Bs)[SKW],
                                          float c[2][8][4],
                                          int warp_m, int warp_n, int lane) {
    int g = lane >> 2, tig = lane & 3;
    #pragma unroll
    for (int ks = 0; ks < 4; ks++) {
        int k0 = ks * 16;
        uint32_t a[2][4], b[8][2];
        #pragma unroll
        for (int mt = 0; mt < 2; mt++) {
            int r = warp_m * 32 + mt * 16 + g;
            a[mt][0] = *(const uint32_t*)&As[r][k0 + tig * 2];
            a[mt][1] = *(const uint32_t*)&As[r + 8][k0 + tig * 2];
            a[mt][2] = *(const uint32_t*)&As[r][k0 + tig * 2 + 8];
            a[mt][3] = *(const uint32_t*)&As[r + 8][k0 + tig * 2 + 8];
        }
        #pragma unroll
        for (int nt = 0; nt < 8; nt++) {
            int n = warp_n * 64 + nt * 8 + g;
            b[nt][0] = *(const uint32_t*)&Bs[n][k0 + tig * 2];
            b[nt][1] = *(const uint32_t*)&Bs[n][k0 + tig * 2 + 8];
        }
        #pragma unroll
        for (int mt = 0; mt < 2; mt++)
            #pragma unroll
            for (int nt = 0; nt < 8; nt++)
                mma16816(c[mt][nt], a[mt], b[nt]);
    }
}

// ===================== L4: expand1 = ELU(aggx @ W1_h + b1) + fused dots =====
#define G1_SMEM (4 * CHUNK_B + 4 * 128 * 4)

__global__ __launch_bounds__(256) void expand1_kernel(const float* __restrict__ b1) {
    extern __shared__ char dsm[];
    __half (*Ab[2])[SKW] = {(__half(*)[SKW])dsm, (__half(*)[SKW])(dsm + 2 * CHUNK_B)};
    __half (*Bb[2])[SKW] = {(__half(*)[SKW])(dsm + CHUNK_B),
                            (__half(*)[SKW])(dsm + 3 * CHUNK_B)};
    float* s_b  = (float*)(dsm + 4 * CHUNK_B);
    float* s_vc = s_b + 128;
    float* s_vs = s_vc + 128;
    float* s_vd = s_vs + 128;

    int tid = threadIdx.x;
    int wid = tid >> 5, lane = tid & 31;
    int warp_m = wid & 3, warp_n = wid >> 2;
    int g = lane >> 2, tig = lane & 3;
    int h = blockIdx.x;
    int m0 = blockIdx.y * MT;

    if (tid < 128) {
        s_b[tid]  = b1[h * EMBED + tid];
        s_vc[tid] = g_vc[h * EMBED + tid];
        s_vs[tid] = g_vs[h * EMBED + tid];
        s_vd[tid] = g_vd[h * EMBED + tid];
    }

    float c[2][8][4];
    #pragma unroll
    for (int mt = 0; mt < 2; mt++)
        #pragma unroll
        for (int nt = 0; nt < 8; nt++)
            #pragma unroll
            for (int i = 0; i < 4; i++) c[mt][nt][i] = 0.f;

    float4 pa[4], pb[4];
    fetch_chunk(g_ax, HC, m0, h * EMBED, pa, tid);
    fetch_chunk(g_w1t, EMBED, h * 128, 0, pb, tid);
    #pragma unroll
    for (int it = 0; it < 2; it++) {
        stash_chunk(pa, Ab[it & 1], tid);
        stash_chunk(pb, Bb[it & 1], tid);
        __syncthreads();
        if (it == 0) {
            fetch_chunk(g_ax, HC, m0, h * EMBED + 64, pa, tid);
            fetch_chunk(g_w1t, EMBED, h * 128, 64, pb, tid);
        }
        mma_chunk(Ab[it & 1], Bb[it & 1], c, warp_m, warp_n, lane);
        __syncthreads();
    }

    // epilogue: bias + ELU + dot partials against v-slices (no x2 store)
    float pc[4] = {0.f, 0.f, 0.f, 0.f};
    float ps[4] = {0.f, 0.f, 0.f, 0.f};
    float pd[4] = {0.f, 0.f, 0.f, 0.f};
    #pragma unroll
    for (int mt = 0; mt < 2; mt++) {
        #pragma unroll
        for (int nt = 0; nt < 8; nt++) {
            int col = warp_n * 64 + nt * 8 + tig * 2;
            float* cc = c[mt][nt];
            #pragma unroll
            for (int q = 0; q < 2; q++) {
                float v0 = cc[q * 2 + 0] + s_b[col];
                float v1 = cc[q * 2 + 1] + s_b[col + 1];
                v0 = v0 > 0.f ? v0 : (__expf(v0) - 1.f);
                v1 = v1 > 0.f ? v1 : (__expf(v1) - 1.f);
                int slot = mt * 2 + q;
                pc[slot] += v0 * s_vc[col] + v1 * s_vc[col + 1];
                ps[slot] += v0 * s_vs[col] + v1 * s_vs[col + 1];
                pd[slot] += v0 * s_vd[col] + v1 * s_vd[col + 1];
            }
        }
    }
    #pragma unroll
    for (int o = 1; o <= 2; o <<= 1) {
        #pragma unroll
        for (int s = 0; s < 4; s++) {
            pc[s] += __shfl_xor_sync(0xffffffffu, pc[s], o);
            ps[s] += __shfl_xor_sync(0xffffffffu, ps[s], o);
            pd[s] += __shfl_xor_sync(0xffffffffu, pd[s], o);
        }
    }
    if (tig == 0) {
        #pragma unroll
        for (int mt = 0; mt < 2; mt++)
            #pragma unroll
            for (int q = 0; q < 2; q++) {
                int row = m0 + warp_m * 32 + mt * 16 + q * 8 + g;
                int slot = mt * 2 + q;
                atomicAdd(&g_c2[row], pc[slot]);
                atomicAdd(&g_als2[row], ps[slot]);
                atomicAdd(&g_ald2[row], pd[slot]);
            }
    }
}

// ===================== L5: agg2 scalar softmax + classifier =================
__global__ void agg2_kernel(float* __restrict__ out, int n) {
    int node = blockIdx.x * 8 + (threadIdx.x >> 5);
    if (node >= n) return;
    int lane = threadIdx.x & 31;
    int beg = g_rowptr[node];
    int deg = g_rowptr[node + 1] - beg;
    float ad = g_ald2[node];

    float m = M_SENT, s = 0.f, acc = 0.f;
    for (int j = lane; j < deg; j += 32) {
        int src = __ldg(&g_col[beg + j]);
        float lg = __ldg(&g_als2[src]) + ad;
        lg = lg > 0.f ? lg : NEG_SLOPE * lg;
        float c2 = __ldg(&g_c2[src]);
        if (lg > m) {
            float sc = __expf(m - lg);
            s = s * sc + 1.f;
            acc = acc * sc + c2;
            m = lg;
        } else {
            float p = __expf(lg - m);
            s += p;
            acc += p * c2;
        }
    }
    #pragma unroll
    for (int o = 16; o > 0; o >>= 1) {
        float om = __shfl_xor_sync(0xffffffffu, m, o);
        float os = __shfl_xor_sync(0xffffffffu, s, o);
        float oa = __shfl_xor_sync(0xffffffffu, acc, o);
        float nm = fmaxf(m, om);
        float e1 = __expf(m - nm), e2 = __expf(om - nm);
        s = s * e1 + os * e2;
        acc = acc * e1 + oa * e2;
        m = nm;
    }
    if (lane == 0) out[node] = acc / (s + 1e-16f) + g_const2;
}

// ===================== launch ===============================================
extern "C" void kernel_launch(void* const* d_in, const int* in_sizes, int n_in,
                              void* d_out, int out_size) {
    const float* x   = (const float*)d_in[0];
    const void*  ei  = d_in[1];
    const float* W1  = (const float*)d_in[2];
    const float* as1 = (const float*)d_in[3];
    const float* ad1 = (const float*)d_in[4];
    const float* b1  = (const float*)d_in[5];
    const float* W2  = (const float*)d_in[6];
    const float* as2 = (const float*)d_in[7];
    const float* ad2 = (const float*)d_in[8];
    const float* b2  = (const float*)d_in[9];
    const float* Wc  = (const float*)d_in[10];
    const float* bc  = (const float*)d_in[11];
    float* out = (float*)d_out;

    int E = in_sizes[1] / 2;
    int n = in_sizes[0] / EMBED;
    int mtiles = (n + MT - 1) / MT;

    cudaFuncSetAttribute(expand1_kernel, cudaFuncAttributeMaxDynamicSharedMemorySize, G1_SMEM);

    int decode_blocks = (2 * E + 255) / 256;
    prep_decode_kernel<<<NB_PRE + decode_blocks, 256>>>(W1, W2, as1, ad1, as2, ad2,
                                                        b2, Wc, bc, ei, E);       // 0
    scan_logits_kernel<<<1 + (n + 31) / 32, 1024>>>(x, n);                        // 1
    fill_kernel<<<(E + MPAD + 255) / 256, 256>>>(E, n);                           // 2
    agg1_kernel<<<n, 128>>>(x);                                                   // 3 <- profiled
    expand1_kernel<<<dim3(HEADS, mtiles), 256, G1_SMEM>>>(b1);                    // 4
    agg2_kernel<<<(n + 7) / 8, 256>>>(out, n);                                    // 5
}